// round 8
// baseline (speedup 1.0000x reference)
#include <cuda_runtime.h>
#include <math.h>
#include <stdint.h>

#define ETHREADS 384
#define EWARPS 12
#define FTHREADS 352
#define FWARPS 11
#define LP_BLOCKS 1024
#define MAXB 2097152
#define MAXBLK 16384

// ---------------- encoder smem word-offsets ----------------
#define EWH   0          // u32: L1 1536 | L2 4096 | L3 2048 = 7680
#define EWL   7680
#define EPAR  15360      // f32: b1,g1,bb1,b2,g2,bb2 (64 ea), b3(32) = 416
#define EINH  15776      // u32: EWARPS x 16 x 28
#define EINL  21152
#define EWKH  26528      // u32/f32: EWARPS x 16 x 68
#define EWKL  39584
#define ENC_SMW 52640    // words (210560 B)

// ---------------- flow smem word-offsets ----------------
#define FWH   0          // u32: F1 2560 | F2 4096 | F3 1536 = 8192
#define FWL   8192
#define FBI   16384      // f32: fb1(64), fb2(64), fb3(24 pad 32) = 160
#define FCXH  16544      // u32: FWARPS x 16 x 44
#define FCXL  24288
#define FWKH  32032      // u32/f32: FWARPS x 16 x 68
#define FWKL  44000
#define FLOW_SMW 55968   // words (223872 B)

__device__ float g_z[MAXB];
__device__ float g_ladj[MAXB];
__device__ float g_block_sums[MAXBLK];

// ---------------- tf32 helpers ----------------
__device__ __forceinline__ uint32_t f2tf(float x) {
    uint32_t r;
    asm("cvt.rna.tf32.f32 %0, %1;" : "=r"(r) : "f"(x));
    return r;
}
__device__ __forceinline__ void split_tf(float v, uint32_t& hi, uint32_t& lo) {
    hi = f2tf(v);
    lo = f2tf(v - __uint_as_float(hi));
}
__device__ __forceinline__ void mma_tf32(
    float& c0, float& c1, float& c2, float& c3,
    uint32_t a0, uint32_t a1, uint32_t a2, uint32_t a3,
    uint32_t b0, uint32_t b1)
{
    asm volatile(
        "mma.sync.aligned.m16n8k8.row.col.f32.tf32.tf32.f32 "
        "{%0,%1,%2,%3}, {%4,%5,%6,%7}, {%8,%9}, {%0,%1,%2,%3};\n"
        : "+f"(c0), "+f"(c1), "+f"(c2), "+f"(c3)
        : "r"(a0), "r"(a1), "r"(a2), "r"(a3), "r"(b0), "r"(b1));
}

// Load split A fragments (hi/lo) from u32 tiles.
template<int KS>
__device__ __forceinline__ void load_af2(uint32_t ah[KS][4], uint32_t al[KS][4],
                                         const uint32_t* __restrict__ th,
                                         const uint32_t* __restrict__ tl,
                                         int RS, int g, int tg) {
#pragma unroll
    for (int ks = 0; ks < KS; ks++) {
        int o0 = g * RS + ks * 8 + tg;
        int o1 = (g + 8) * RS + ks * 8 + tg;
        ah[ks][0] = th[o0];     ah[ks][1] = th[o1];
        ah[ks][2] = th[o0 + 4]; ah[ks][3] = th[o1 + 4];
        al[ks][0] = tl[o0];     al[ks][1] = tl[o1];
        al[ks][2] = tl[o0 + 4]; al[ks][3] = tl[o1 + 4];
    }
}

// 3xTF32 GEMM tile: acc += Ah*Bh + Al*Bh + Ah*Bl  (per nt column-tile).
template<int KS>
__device__ __forceinline__ void mma3_cols(float c[4],
                                          const uint32_t ah[KS][4],
                                          const uint32_t al[KS][4],
                                          const uint32_t* __restrict__ wh,
                                          const uint32_t* __restrict__ wl,
                                          int lane) {
#pragma unroll
    for (int ks = 0; ks < KS; ks++) {
        uint32_t bh0 = wh[ks * 64 + lane];
        uint32_t bh1 = wh[ks * 64 + 32 + lane];
        uint32_t bl0 = wl[ks * 64 + lane];
        uint32_t bl1 = wl[ks * 64 + 32 + lane];
        mma_tf32(c[0], c[1], c[2], c[3],
                 al[ks][0], al[ks][1], al[ks][2], al[ks][3], bh0, bh1);
        mma_tf32(c[0], c[1], c[2], c[3],
                 ah[ks][0], ah[ks][1], ah[ks][2], ah[ks][3], bl0, bl1);
        mma_tf32(c[0], c[1], c[2], c[3],
                 ah[ks][0], ah[ks][1], ah[ks][2], ah[ks][3], bh0, bh1);
    }
}

// GEMM -> split-store into hi/lo u32 tiles (optional ReLU).
template<int KS, int NT, bool RELU>
__device__ __forceinline__ void gemm3_store_split(
    const uint32_t ah[KS][4], const uint32_t al[KS][4],
    const uint32_t* __restrict__ wh, const uint32_t* __restrict__ wl,
    const float* __restrict__ bias,
    uint32_t* __restrict__ oh, uint32_t* __restrict__ ol,
    int RS, int lane, int g, int tg)
{
#pragma unroll
    for (int nt = 0; nt < NT; nt++) {
        int colb = nt * 8 + 2 * tg;
        float2 bb = *(const float2*)&bias[colb];
        float c[4] = {bb.x, bb.y, bb.x, bb.y};
        mma3_cols<KS>(c, ah, al, wh + nt * KS * 64, wl + nt * KS * 64, lane);
        if (RELU) {
#pragma unroll
            for (int q = 0; q < 4; q++) c[q] = fmaxf(c[q], 0.f);
        }
        uint32_t h0, l0, h1, l1;
        split_tf(c[0], h0, l0); split_tf(c[1], h1, l1);
        *(uint2*)&oh[g * RS + colb] = make_uint2(h0, h1);
        *(uint2*)&ol[g * RS + colb] = make_uint2(l0, l1);
        split_tf(c[2], h0, l0); split_tf(c[3], h1, l1);
        *(uint2*)&oh[(g + 8) * RS + colb] = make_uint2(h0, h1);
        *(uint2*)&ol[(g + 8) * RS + colb] = make_uint2(l0, l1);
    }
}

// GEMM -> plain fp32 store (final layers).
template<int KS, int NT>
__device__ __forceinline__ void gemm3_store_f32(
    const uint32_t ah[KS][4], const uint32_t al[KS][4],
    const uint32_t* __restrict__ wh, const uint32_t* __restrict__ wl,
    const float* __restrict__ bias,
    float* __restrict__ out, int RS, int lane, int g, int tg)
{
#pragma unroll
    for (int nt = 0; nt < NT; nt++) {
        int colb = nt * 8 + 2 * tg;
        float2 bb = *(const float2*)&bias[colb];
        float c[4] = {bb.x, bb.y, bb.x, bb.y};
        mma3_cols<KS>(c, ah, al, wh + nt * KS * 64, wl + nt * KS * 64, lane);
        *(float2*)&out[g * RS + colb] = make_float2(c[0], c[1]);
        *(float2*)&out[(g + 8) * RS + colb] = make_float2(c[2], c[3]);
    }
}

// GEMM keeping accumulators (for LN epilogue).
template<int KS, int NT>
__device__ __forceinline__ void gemm3_acc(
    const uint32_t ah[KS][4], const uint32_t al[KS][4],
    const uint32_t* __restrict__ wh, const uint32_t* __restrict__ wl,
    const float* __restrict__ bias, float acc[NT][4], int lane, int tg)
{
#pragma unroll
    for (int nt = 0; nt < NT; nt++) {
        int colb = nt * 8 + 2 * tg;
        float2 bb = *(const float2*)&bias[colb];
        acc[nt][0] = bb.x; acc[nt][1] = bb.y;
        acc[nt][2] = bb.x; acc[nt][3] = bb.y;
        mma3_cols<KS>(acc[nt], ah, al,
                      wh + nt * KS * 64, wl + nt * KS * 64, lane);
    }
}

__device__ __forceinline__ float gelu_exact(float v) {
    return 0.5f * v * (1.f + erff(v * 0.70710678118654752f));
}

// In-register LN (quad shfl) + GELU, split-store to hi/lo tiles.
__device__ __forceinline__ void ln_gelu_store_split(
    float acc[8][4], const float* __restrict__ lg, const float* __restrict__ lb,
    uint32_t* __restrict__ oh, uint32_t* __restrict__ ol,
    int RS, int g, int tg)
{
    float s0 = 0.f, s1 = 0.f;
#pragma unroll
    for (int nt = 0; nt < 8; nt++) {
        s0 += acc[nt][0] + acc[nt][1];
        s1 += acc[nt][2] + acc[nt][3];
    }
    s0 += __shfl_xor_sync(0xffffffffu, s0, 1);
    s0 += __shfl_xor_sync(0xffffffffu, s0, 2);
    s1 += __shfl_xor_sync(0xffffffffu, s1, 1);
    s1 += __shfl_xor_sync(0xffffffffu, s1, 2);
    float mu0 = s0 * (1.f / 64.f), mu1 = s1 * (1.f / 64.f);
    float v0 = 0.f, v1 = 0.f;
#pragma unroll
    for (int nt = 0; nt < 8; nt++) {
        float d;
        d = acc[nt][0] - mu0; v0 = fmaf(d, d, v0);
        d = acc[nt][1] - mu0; v0 = fmaf(d, d, v0);
        d = acc[nt][2] - mu1; v1 = fmaf(d, d, v1);
        d = acc[nt][3] - mu1; v1 = fmaf(d, d, v1);
    }
    v0 += __shfl_xor_sync(0xffffffffu, v0, 1);
    v0 += __shfl_xor_sync(0xffffffffu, v0, 2);
    v1 += __shfl_xor_sync(0xffffffffu, v1, 1);
    v1 += __shfl_xor_sync(0xffffffffu, v1, 2);
    float inv0 = rsqrtf(v0 * (1.f / 64.f) + 1e-5f);
    float inv1 = rsqrtf(v1 * (1.f / 64.f) + 1e-5f);
#pragma unroll
    for (int nt = 0; nt < 8; nt++) {
        int colb = nt * 8 + 2 * tg;
        float2 gg = *(const float2*)&lg[colb];
        float2 be = *(const float2*)&lb[colb];
        float e0 = gelu_exact((acc[nt][0] - mu0) * inv0 * gg.x + be.x);
        float e1 = gelu_exact((acc[nt][1] - mu0) * inv0 * gg.y + be.y);
        float e2 = gelu_exact((acc[nt][2] - mu1) * inv1 * gg.x + be.x);
        float e3 = gelu_exact((acc[nt][3] - mu1) * inv1 * gg.y + be.y);
        uint32_t h0, l0, h1, l1;
        split_tf(e0, h0, l0); split_tf(e1, h1, l1);
        *(uint2*)&oh[g * RS + colb] = make_uint2(h0, h1);
        *(uint2*)&ol[g * RS + colb] = make_uint2(l0, l1);
        split_tf(e2, h0, l0); split_tf(e3, h1, l1);
        *(uint2*)&oh[(g + 8) * RS + colb] = make_uint2(h0, h1);
        *(uint2*)&ol[(g + 8) * RS + colb] = make_uint2(l0, l1);
    }
}

// ---------------- rational-quadratic spline ----------------
__device__ __forceinline__ void rqs_step(const float* __restrict__ p3,
                                         float& z, float& ladj) {
    const float* pw = p3;
    const float* ph = p3 + 8;
    const float* pd = p3 + 16;
    float ew[8], eh[8];
    float mw = pw[0], mh = ph[0];
#pragma unroll
    for (int n = 1; n < 8; n++) {
        mw = fmaxf(mw, pw[n]); mh = fmaxf(mh, ph[n]);
    }
    float sw = 0.f, sh = 0.f;
#pragma unroll
    for (int n = 0; n < 8; n++) {
        ew[n] = __expf(pw[n] - mw); sw += ew[n];
        eh[n] = __expf(ph[n] - mh); sh += eh[n];
    }
    float aw = __fdividef(10.0f, sw), ah = __fdividef(10.0f, sh);
    float xk[9], yk[9], dk[9];
    xk[0] = -5.f; yk[0] = -5.f; dk[0] = 1.f; dk[8] = 1.f;
#pragma unroll
    for (int n = 0; n < 8; n++) {
        xk[n + 1] = fmaf(ew[n], aw, xk[n]);
        yk[n + 1] = fmaf(eh[n], ah, yk[n]);
    }
#pragma unroll
    for (int n = 0; n < 7; n++) {
        float v = pd[n];
        dk[n + 1] = fmaxf(v, 0.f) + log1pf(__expf(-fabsf(v)));
    }
    bool inside = (z > -5.f) && (z < 5.f);
    float xc = fminf(fmaxf(z, -5.f), 5.f);
    float x0 = xk[0], x1 = xk[1], y0 = yk[0], y1 = yk[1];
    float d0 = dk[0], d1 = dk[1];
#pragma unroll
    for (int m = 1; m < 8; m++) {
        bool cc = xc >= xk[m];
        x0 = cc ? xk[m] : x0;     x1 = cc ? xk[m + 1] : x1;
        y0 = cc ? yk[m] : y0;     y1 = cc ? yk[m + 1] : y1;
        d0 = cc ? dk[m] : d0;     d1 = cc ? dk[m + 1] : d1;
    }
    float wk = x1 - x0, hk = y1 - y0;
    float s  = __fdividef(hk, wk);
    float xi = __fdividef(xc - x0, wk);
    float om = 1.f - xi;
    float den = fmaf(fmaf(-2.f, s, d0 + d1), xi * om, s);
    float yin = y0 + hk * __fdividef(s * xi * xi + d0 * xi * om, den);
    float A   = fmaf(d1 * xi, xi, fmaf(2.f * s * xi, om, d0 * om * om));
    float ldin = __logf(__fdividef((s * s) * A, den * den));
    z    = inside ? yin : z;
    ladj = inside ? (ladj + ldin) : ladj;
}

// Stage W[K][N] row-major into split tf32 fragment-linear order.
template<int NTHREADS>
__device__ __forceinline__ void stage_frags2(uint32_t* __restrict__ dh,
                                             uint32_t* __restrict__ dl,
                                             const float* __restrict__ W,
                                             int K, int N, int KS, int NT,
                                             int tid) {
    int total = NT * KS * 64;
    for (int i = tid; i < total; i += NTHREADS) {
        int lane = i & 31;
        int reg  = (i >> 5) & 1;
        int rest = i >> 6;
        int ks = rest % KS, nt = rest / KS;
        int k = ks * 8 + (lane & 3) + reg * 4;
        int n = nt * 8 + (lane >> 2);
        float v = (k < K && n < N) ? W[k * N + n] : 0.f;
        uint32_t h, l;
        split_tf(v, h, l);
        dh[i] = h; dl[i] = l;
    }
}

// ======================= encoder =======================
__global__ __launch_bounds__(ETHREADS, 1)
void encoder_kernel(
    const float* __restrict__ metadata, const float* __restrict__ mask,
    const float* __restrict__ eW1, const float* __restrict__ eb1,
    const float* __restrict__ eg1, const float* __restrict__ ebt1,
    const float* __restrict__ eW2, const float* __restrict__ eb2,
    const float* __restrict__ eg2, const float* __restrict__ ebt2,
    const float* __restrict__ eW3, const float* __restrict__ eb3,
    float* __restrict__ out_latent, int B)
{
    extern __shared__ float sm[];
    uint32_t* smu = (uint32_t*)sm;
    const int tid = threadIdx.x;

    stage_frags2<ETHREADS>(smu + EWH,        smu + EWL,        eW1, 22, 64, 3, 8, tid);
    stage_frags2<ETHREADS>(smu + EWH + 1536, smu + EWL + 1536, eW2, 64, 64, 8, 8, tid);
    stage_frags2<ETHREADS>(smu + EWH + 5632, smu + EWL + 5632, eW3, 64, 32, 8, 4, tid);
    for (int i = tid; i < 64; i += ETHREADS) {
        sm[EPAR + i]       = eb1[i];
        sm[EPAR + 64 + i]  = eg1[i];
        sm[EPAR + 128 + i] = ebt1[i];
        sm[EPAR + 192 + i] = eb2[i];
        sm[EPAR + 256 + i] = eg2[i];
        sm[EPAR + 320 + i] = ebt2[i];
    }
    for (int i = tid; i < 32; i += ETHREADS) sm[EPAR + 384 + i] = eb3[i];
    __syncthreads();

    const int wid = tid >> 5, lane = tid & 31;
    const int g = lane >> 2, tg = lane & 3;
    uint32_t* inh = smu + EINH + wid * 448;    // 16 x 28
    uint32_t* inl = smu + EINL + wid * 448;
    uint32_t* wkh = smu + EWKH + wid * 1088;   // 16 x 68
    uint32_t* wkl = smu + EWKL + wid * 1088;
    float*    wkf = (float*)wkh;

    for (int rb = ((int)blockIdx.x * EWARPS + wid) * 16; rb < B;
         rb += (int)gridDim.x * EWARPS * 16) {
        for (int i = lane; i < 176; i += 32) {
            int r = i / 11, c = i % 11;
            int gr = min(rb + r, B - 1);
            uint32_t h, l;
            split_tf(metadata[(size_t)gr * 11 + c], h, l);
            inh[r * 28 + c] = h; inl[r * 28 + c] = l;
            split_tf(mask[(size_t)gr * 11 + c], h, l);
            inh[r * 28 + 11 + c] = h; inl[r * 28 + 11 + c] = l;
        }
        if (lane < 16) {
            inh[lane * 28 + 22] = 0; inh[lane * 28 + 23] = 0;
            inl[lane * 28 + 22] = 0; inl[lane * 28 + 23] = 0;
        }
        __syncwarp();

        {   // L1 + LN + GELU
            uint32_t ah[3][4], al[3][4];
            load_af2<3>(ah, al, inh, inl, 28, g, tg);
            float acc[8][4];
            gemm3_acc<3, 8>(ah, al, smu + EWH, smu + EWL, sm + EPAR,
                            acc, lane, tg);
            ln_gelu_store_split(acc, sm + EPAR + 64, sm + EPAR + 128,
                                wkh, wkl, 68, g, tg);
        }
        __syncwarp();
        {   // L2 + LN + GELU
            uint32_t ah[8][4], al[8][4];
            load_af2<8>(ah, al, wkh, wkl, 68, g, tg);
            float acc[8][4];
            gemm3_acc<8, 8>(ah, al, smu + EWH + 1536, smu + EWL + 1536,
                            sm + EPAR + 192, acc, lane, tg);
            ln_gelu_store_split(acc, sm + EPAR + 256, sm + EPAR + 320,
                                wkh, wkl, 68, g, tg);
        }
        __syncwarp();
        {   // L3 -> latent (fp32)
            uint32_t ah[8][4], al[8][4];
            load_af2<8>(ah, al, wkh, wkl, 68, g, tg);
            gemm3_store_f32<8, 4>(ah, al, smu + EWH + 5632, smu + EWL + 5632,
                                  sm + EPAR + 384, wkf, 68, lane, g, tg);
        }
        __syncwarp();
        for (int i = lane; i < 128; i += 32) {
            int r = i >> 3, q = i & 7;
            int gr = rb + r;
            if (gr < B)
                *(float4*)&out_latent[(size_t)gr * 32 + 4 * q] =
                    *(const float4*)&wkf[r * 68 + 4 * q];
        }
        __syncwarp();
    }
}

// ======================= one flow transform =======================
__global__ __launch_bounds__(FTHREADS, 1)
void flow_kernel(
    const float* __restrict__ latent, const float* __restrict__ prot,
    const float* __restrict__ age,
    const float* __restrict__ fW1t, const float* __restrict__ fb1t,
    const float* __restrict__ fW2t, const float* __restrict__ fb2t,
    const float* __restrict__ fW3t, const float* __restrict__ fb3t,
    int first, int B)
{
    extern __shared__ float sm[];
    uint32_t* smu = (uint32_t*)sm;
    const int tid = threadIdx.x;

    stage_frags2<FTHREADS>(smu + FWH,        smu + FWL,        fW1t, 33, 64, 5, 8, tid);
    stage_frags2<FTHREADS>(smu + FWH + 2560, smu + FWL + 2560, fW2t, 64, 64, 8, 8, tid);
    stage_frags2<FTHREADS>(smu + FWH + 6656, smu + FWL + 6656, fW3t, 64, 23, 8, 3, tid);
    for (int i = tid; i < 64; i += FTHREADS) {
        sm[FBI + i]      = fb1t[i];
        sm[FBI + 64 + i] = fb2t[i];
    }
    for (int i = tid; i < 32; i += FTHREADS)
        sm[FBI + 128 + i] = (i < 23) ? fb3t[i] : 0.f;
    __syncthreads();

    const int wid = tid >> 5, lane = tid & 31;
    const int g = lane >> 2, tg = lane & 3;
    uint32_t* cxh = smu + FCXH + wid * 704;   // 16 x 44
    uint32_t* cxl = smu + FCXL + wid * 704;
    uint32_t* wkh = smu + FWKH + wid * 1088;  // 16 x 68
    uint32_t* wkl = smu + FWKL + wid * 1088;
    float*    wkf = (float*)wkh;

    for (int rb = ((int)blockIdx.x * FWARPS + wid) * 16; rb < B;
         rb += (int)gridDim.x * FWARPS * 16) {
        for (int i = lane; i < 128; i += 32) {
            int r = i >> 3, q = i & 7;
            int gr = min(rb + r, B - 1);
            float4 a = *(const float4*)&latent[(size_t)gr * 32 + 4 * q];
            uint32_t h, l;
            split_tf(a.x, h, l); cxh[r * 44 + 4 * q]     = h; cxl[r * 44 + 4 * q]     = l;
            split_tf(a.y, h, l); cxh[r * 44 + 4 * q + 1] = h; cxl[r * 44 + 4 * q + 1] = l;
            split_tf(a.z, h, l); cxh[r * 44 + 4 * q + 2] = h; cxl[r * 44 + 4 * q + 2] = l;
            split_tf(a.w, h, l); cxh[r * 44 + 4 * q + 3] = h; cxl[r * 44 + 4 * q + 3] = l;
        }
        float z = 0.f, la = 0.f;
        if (lane < 16) {
            int gr = min(rb + lane, B - 1);
            uint32_t h, l;
            split_tf(prot[gr], h, l);
            cxh[lane * 44 + 32] = h; cxl[lane * 44 + 32] = l;
#pragma unroll
            for (int c = 33; c < 40; c++) {
                cxh[lane * 44 + c] = 0; cxl[lane * 44 + c] = 0;
            }
            if (first) { z = age[gr]; la = 0.f; }
            else       { z = g_z[gr]; la = g_ladj[gr]; }
        }
        __syncwarp();

        {   // F1 (ReLU)
            uint32_t ah[5][4], al[5][4];
            load_af2<5>(ah, al, cxh, cxl, 44, g, tg);
            gemm3_store_split<5, 8, true>(ah, al, smu + FWH, smu + FWL,
                                          sm + FBI, wkh, wkl, 68, lane, g, tg);
        }
        __syncwarp();
        {   // F2 (ReLU)
            uint32_t ah[8][4], al[8][4];
            load_af2<8>(ah, al, wkh, wkl, 68, g, tg);
            gemm3_store_split<8, 8, true>(ah, al, smu + FWH + 2560,
                                          smu + FWL + 2560, sm + FBI + 64,
                                          wkh, wkl, 68, lane, g, tg);
        }
        __syncwarp();
        {   // F3 -> fp32 params
            uint32_t ah[8][4], al[8][4];
            load_af2<8>(ah, al, wkh, wkl, 68, g, tg);
            gemm3_store_f32<8, 3>(ah, al, smu + FWH + 6656, smu + FWL + 6656,
                                  sm + FBI + 128, wkf, 68, lane, g, tg);
        }
        __syncwarp();
        if (lane < 16) {
            int r = rb + lane;
            if (r < B) {
                float p3[24];
#pragma unroll
                for (int c = 0; c < 24; c++) p3[c] = wkf[lane * 68 + c];
                rqs_step(p3, z, la);
                g_z[r] = z;
                g_ladj[r] = la;
            }
        }
        __syncwarp();
    }
}

// ======================= log_prob + reduction =======================
__global__ __launch_bounds__(256, 1)
void lp_kernel(float* __restrict__ out_lp, int B) {
    __shared__ float red[256];
    float lsum = 0.f;
    for (int row = blockIdx.x * 256 + threadIdx.x; row < B;
         row += gridDim.x * 256) {
        float z = g_z[row];
        float lp = fmaf(-0.5f, z * z, -0.91893853320467274f) + g_ladj[row];
        out_lp[row] = lp;
        lsum += lp;
    }
    red[threadIdx.x] = lsum;
    __syncthreads();
#pragma unroll
    for (int off = 128; off > 0; off >>= 1) {
        if (threadIdx.x < off) red[threadIdx.x] += red[threadIdx.x + off];
        __syncthreads();
    }
    if (threadIdx.x == 0) g_block_sums[blockIdx.x] = red[0];
}

__global__ void finalize_kernel(int B, float* __restrict__ out_nll) {
    __shared__ double red[256];
    double s = 0.0;
    for (int i = threadIdx.x; i < LP_BLOCKS; i += 256)
        s += (double)g_block_sums[i];
    red[threadIdx.x] = s;
    __syncthreads();
#pragma unroll
    for (int off = 128; off > 0; off >>= 1) {
        if (threadIdx.x < off) red[threadIdx.x] += red[threadIdx.x + off];
        __syncthreads();
    }
    if (threadIdx.x == 0)
        out_nll[0] = (float)(-red[0] / (double)B);
}

extern "C" void kernel_launch(void* const* d_in, const int* in_sizes, int n_in,
                              void* d_out, int out_size) {
    const float* metadata = (const float*)d_in[0];
    const float* prot     = (const float*)d_in[1];
    const float* age      = (const float*)d_in[2];
    const float* mask     = (const float*)d_in[3];
    const float* eW1  = (const float*)d_in[4];
    const float* eb1  = (const float*)d_in[5];
    const float* eg1  = (const float*)d_in[6];
    const float* ebt1 = (const float*)d_in[7];
    const float* eW2  = (const float*)d_in[8];
    const float* eb2  = (const float*)d_in[9];
    const float* eg2  = (const float*)d_in[10];
    const float* ebt2 = (const float*)d_in[11];
    const float* eW3  = (const float*)d_in[12];
    const float* eb3  = (const float*)d_in[13];
    const float* fW1  = (const float*)d_in[14];
    const float* fb1  = (const float*)d_in[15];
    const float* fW2  = (const float*)d_in[16];
    const float* fb2  = (const float*)d_in[17];
    const float* fW3  = (const float*)d_in[18];
    const float* fb3  = (const float*)d_in[19];

    const int B = in_sizes[1];
    float* out = (float*)d_out;
    float* out_latent = out;
    float* out_lp     = out + (size_t)B * 32;
    float* out_nll    = out + (size_t)B * 33;

    int sms = 148;
    cudaDeviceProp prop;
    if (cudaGetDeviceProperties(&prop, 0) == cudaSuccess)
        sms = prop.multiProcessorCount;

    size_t enc_smem  = (size_t)ENC_SMW * 4;
    size_t flow_smem = (size_t)FLOW_SMW * 4;
    cudaFuncSetAttribute(encoder_kernel,
                         cudaFuncAttributeMaxDynamicSharedMemorySize,
                         (int)enc_smem);
    cudaFuncSetAttribute(flow_kernel,
                         cudaFuncAttributeMaxDynamicSharedMemorySize,
                         (int)flow_smem);

    // My launch idx: enc(0) f0(1) f1(2) f2(3) f3(4) lp(5) fin(6).
    // Harness offset is 2 launches, so ncu -s 5 profiles my idx 3 = f2.
    encoder_kernel<<<sms, ETHREADS, enc_smem>>>(
        metadata, mask, eW1, eb1, eg1, ebt1, eW2, eb2, eg2, ebt2, eW3, eb3,
        out_latent, B);

    for (int t = 0; t < 4; t++) {
        flow_kernel<<<sms, FTHREADS, flow_smem>>>(
            out_latent, prot, age,
            fW1 + (size_t)t * 33 * 64, fb1 + (size_t)t * 64,
            fW2 + (size_t)t * 64 * 64, fb2 + (size_t)t * 64,
            fW3 + (size_t)t * 64 * 23, fb3 + (size_t)t * 23,
            (t == 0) ? 1 : 0, B);
    }

    lp_kernel<<<LP_BLOCKS, 256>>>(out_lp, B);
    finalize_kernel<<<1, 256>>>(B, out_nll);
}

// round 9
// speedup vs baseline: 1.7172x; 1.7172x over previous
#include <cuda_runtime.h>
#include <math.h>
#include <stdint.h>

#define ETHREADS 576
#define EWARPS 18
#define FTHREADS 576
#define FWARPS 18
#define MAXB 2097152
#define MAXBLK 16384

// ---------------- encoder smem word-offsets ----------------
#define EWH   0          // u32 hi frags: L1 1536 | L2 4096 | L3 2048 = 7680
#define EPAR  7680       // f32: b1,g1,bb1,b2,g2,bb2 (64 ea), b3(32) = 416
#define EIN   8096       // f32: EWARPS x 16 x 28
#define EWK   16160      // f32: EWARPS x 16 x 68
#define ENC_SMW 35744    // words (142976 B)

// ---------------- flow smem word-offsets ----------------
#define FWH   0          // u32 hi frags: F1 2560 | F2 4096 | F3 1536 = 8192
#define FBI   8192       // f32: fb1(64), fb2(64), fb3(24 pad 32) = 160
#define FCX   8352       // f32: FWARPS x 16 x 44
#define FWK   21024      // f32: FWARPS x 16 x 68
#define FRED  40608      // FTHREADS
#define FLOW_SMW 41184   // words (164736 B)

__device__ float g_z[MAXB];
__device__ float g_ladj[MAXB];
__device__ float g_block_sums[MAXBLK];

// ---------------- tf32 helpers ----------------
__device__ __forceinline__ uint32_t f2tf(float x) {
    uint32_t r;
    asm("cvt.rna.tf32.f32 %0, %1;" : "=r"(r) : "f"(x));
    return r;
}
// A-side split: hi = raw fp32 bits (HW truncates mantissa to tf32),
// lo = v - trunc(v) (exact in fp32).
__device__ __forceinline__ void split_a(float v, uint32_t& hi, uint32_t& lo) {
    uint32_t b = __float_as_uint(v);
    hi = b;
    float t = __uint_as_float(b & 0xFFFFE000u);
    lo = __float_as_uint(v - t);
}
__device__ __forceinline__ void mma_tf32(
    float& c0, float& c1, float& c2, float& c3,
    uint32_t a0, uint32_t a1, uint32_t a2, uint32_t a3,
    uint32_t b0, uint32_t b1)
{
    asm volatile(
        "mma.sync.aligned.m16n8k8.row.col.f32.tf32.tf32.f32 "
        "{%0,%1,%2,%3}, {%4,%5,%6,%7}, {%8,%9}, {%0,%1,%2,%3};\n"
        : "+f"(c0), "+f"(c1), "+f"(c2), "+f"(c3)
        : "r"(a0), "r"(a1), "r"(a2), "r"(a3), "r"(b0), "r"(b1));
}

// Load split A fragments from an fp32 tile.
template<int KS>
__device__ __forceinline__ void load_af(uint32_t ah[KS][4], uint32_t al[KS][4],
                                        const float* __restrict__ t,
                                        int RS, int g, int tg) {
#pragma unroll
    for (int ks = 0; ks < KS; ks++) {
        int o0 = g * RS + ks * 8 + tg;
        int o1 = (g + 8) * RS + ks * 8 + tg;
        split_a(t[o0],     ah[ks][0], al[ks][0]);
        split_a(t[o1],     ah[ks][1], al[ks][1]);
        split_a(t[o0 + 4], ah[ks][2], al[ks][2]);
        split_a(t[o1 + 4], ah[ks][3], al[ks][3]);
    }
}

// 2-term GEMM column-tile: acc += Al*Bh + Ah*Bh  (A fully compensated).
template<int KS>
__device__ __forceinline__ void mma2_cols(float c[4],
                                          const uint32_t ah[KS][4],
                                          const uint32_t al[KS][4],
                                          const uint32_t* __restrict__ wh,
                                          int lane) {
#pragma unroll
    for (int ks = 0; ks < KS; ks++) {
        uint32_t b0 = wh[ks * 64 + lane];
        uint32_t b1 = wh[ks * 64 + 32 + lane];
        mma_tf32(c[0], c[1], c[2], c[3],
                 al[ks][0], al[ks][1], al[ks][2], al[ks][3], b0, b1);
        mma_tf32(c[0], c[1], c[2], c[3],
                 ah[ks][0], ah[ks][1], ah[ks][2], ah[ks][3], b0, b1);
    }
}

// GEMM -> fp32 tile store (optional ReLU).
template<int KS, int NT, bool RELU>
__device__ __forceinline__ void gemm2_store(
    const uint32_t ah[KS][4], const uint32_t al[KS][4],
    const uint32_t* __restrict__ wh, const float* __restrict__ bias,
    float* __restrict__ out, int RS, int lane, int g, int tg)
{
#pragma unroll
    for (int nt = 0; nt < NT; nt++) {
        int colb = nt * 8 + 2 * tg;
        float2 bb = *(const float2*)&bias[colb];
        float c[4] = {bb.x, bb.y, bb.x, bb.y};
        mma2_cols<KS>(c, ah, al, wh + nt * KS * 64, lane);
        if (RELU) {
#pragma unroll
            for (int q = 0; q < 4; q++) c[q] = fmaxf(c[q], 0.f);
        }
        *(float2*)&out[g * RS + colb] = make_float2(c[0], c[1]);
        *(float2*)&out[(g + 8) * RS + colb] = make_float2(c[2], c[3]);
    }
}

// GEMM keeping accumulators (for LN epilogue).
template<int KS, int NT>
__device__ __forceinline__ void gemm2_acc(
    const uint32_t ah[KS][4], const uint32_t al[KS][4],
    const uint32_t* __restrict__ wh, const float* __restrict__ bias,
    float acc[NT][4], int lane, int tg)
{
#pragma unroll
    for (int nt = 0; nt < NT; nt++) {
        int colb = nt * 8 + 2 * tg;
        float2 bb = *(const float2*)&bias[colb];
        acc[nt][0] = bb.x; acc[nt][1] = bb.y;
        acc[nt][2] = bb.x; acc[nt][3] = bb.y;
        mma2_cols<KS>(acc[nt], ah, al, wh + nt * KS * 64, lane);
    }
}

__device__ __forceinline__ float gelu_exact(float v) {
    return 0.5f * v * (1.f + erff(v * 0.70710678118654752f));
}

// In-register LN (quad shfl) + GELU -> fp32 tile store.
__device__ __forceinline__ void ln_gelu_store(
    float acc[8][4], const float* __restrict__ lg, const float* __restrict__ lb,
    float* __restrict__ out, int RS, int g, int tg)
{
    float s0 = 0.f, s1 = 0.f;
#pragma unroll
    for (int nt = 0; nt < 8; nt++) {
        s0 += acc[nt][0] + acc[nt][1];
        s1 += acc[nt][2] + acc[nt][3];
    }
    s0 += __shfl_xor_sync(0xffffffffu, s0, 1);
    s0 += __shfl_xor_sync(0xffffffffu, s0, 2);
    s1 += __shfl_xor_sync(0xffffffffu, s1, 1);
    s1 += __shfl_xor_sync(0xffffffffu, s1, 2);
    float mu0 = s0 * (1.f / 64.f), mu1 = s1 * (1.f / 64.f);
    float v0 = 0.f, v1 = 0.f;
#pragma unroll
    for (int nt = 0; nt < 8; nt++) {
        float d;
        d = acc[nt][0] - mu0; v0 = fmaf(d, d, v0);
        d = acc[nt][1] - mu0; v0 = fmaf(d, d, v0);
        d = acc[nt][2] - mu1; v1 = fmaf(d, d, v1);
        d = acc[nt][3] - mu1; v1 = fmaf(d, d, v1);
    }
    v0 += __shfl_xor_sync(0xffffffffu, v0, 1);
    v0 += __shfl_xor_sync(0xffffffffu, v0, 2);
    v1 += __shfl_xor_sync(0xffffffffu, v1, 1);
    v1 += __shfl_xor_sync(0xffffffffu, v1, 2);
    float inv0 = rsqrtf(v0 * (1.f / 64.f) + 1e-5f);
    float inv1 = rsqrtf(v1 * (1.f / 64.f) + 1e-5f);
#pragma unroll
    for (int nt = 0; nt < 8; nt++) {
        int colb = nt * 8 + 2 * tg;
        float2 gg = *(const float2*)&lg[colb];
        float2 be = *(const float2*)&lb[colb];
        float e0 = gelu_exact((acc[nt][0] - mu0) * inv0 * gg.x + be.x);
        float e1 = gelu_exact((acc[nt][1] - mu0) * inv0 * gg.y + be.y);
        float e2 = gelu_exact((acc[nt][2] - mu1) * inv1 * gg.x + be.x);
        float e3 = gelu_exact((acc[nt][3] - mu1) * inv1 * gg.y + be.y);
        *(float2*)&out[g * RS + colb] = make_float2(e0, e1);
        *(float2*)&out[(g + 8) * RS + colb] = make_float2(e2, e3);
    }
}

// ---------------- rational-quadratic spline ----------------
__device__ __forceinline__ void rqs_step(const float* __restrict__ p3,
                                         float& z, float& ladj) {
    const float* pw = p3;
    const float* ph = p3 + 8;
    const float* pd = p3 + 16;
    float ew[8], eh[8];
    float mw = pw[0], mh = ph[0];
#pragma unroll
    for (int n = 1; n < 8; n++) {
        mw = fmaxf(mw, pw[n]); mh = fmaxf(mh, ph[n]);
    }
    float sw = 0.f, sh = 0.f;
#pragma unroll
    for (int n = 0; n < 8; n++) {
        ew[n] = __expf(pw[n] - mw); sw += ew[n];
        eh[n] = __expf(ph[n] - mh); sh += eh[n];
    }
    float aw = __fdividef(10.0f, sw), ah = __fdividef(10.0f, sh);
    float xk[9], yk[9], dk[9];
    xk[0] = -5.f; yk[0] = -5.f; dk[0] = 1.f; dk[8] = 1.f;
#pragma unroll
    for (int n = 0; n < 8; n++) {
        xk[n + 1] = fmaf(ew[n], aw, xk[n]);
        yk[n + 1] = fmaf(eh[n], ah, yk[n]);
    }
#pragma unroll
    for (int n = 0; n < 7; n++) {
        float v = pd[n];
        dk[n + 1] = fmaxf(v, 0.f) + log1pf(__expf(-fabsf(v)));
    }
    bool inside = (z > -5.f) && (z < 5.f);
    float xc = fminf(fmaxf(z, -5.f), 5.f);
    float x0 = xk[0], x1 = xk[1], y0 = yk[0], y1 = yk[1];
    float d0 = dk[0], d1 = dk[1];
#pragma unroll
    for (int m = 1; m < 8; m++) {
        bool cc = xc >= xk[m];
        x0 = cc ? xk[m] : x0;     x1 = cc ? xk[m + 1] : x1;
        y0 = cc ? yk[m] : y0;     y1 = cc ? yk[m + 1] : y1;
        d0 = cc ? dk[m] : d0;     d1 = cc ? dk[m + 1] : d1;
    }
    float wk = x1 - x0, hk = y1 - y0;
    float s  = __fdividef(hk, wk);
    float xi = __fdividef(xc - x0, wk);
    float om = 1.f - xi;
    float den = fmaf(fmaf(-2.f, s, d0 + d1), xi * om, s);
    float yin = y0 + hk * __fdividef(s * xi * xi + d0 * xi * om, den);
    float A   = fmaf(d1 * xi, xi, fmaf(2.f * s * xi, om, d0 * om * om));
    float ldin = __logf(__fdividef((s * s) * A, den * den));
    z    = inside ? yin : z;
    ladj = inside ? (ladj + ldin) : ladj;
}

// Stage W[K][N] row-major into tf32(hi, rna) fragment-linear order.
template<int NTHREADS>
__device__ __forceinline__ void stage_frags(uint32_t* __restrict__ dh,
                                            const float* __restrict__ W,
                                            int K, int N, int KS, int NT,
                                            int tid) {
    int total = NT * KS * 64;
    for (int i = tid; i < total; i += NTHREADS) {
        int lane = i & 31;
        int reg  = (i >> 5) & 1;
        int rest = i >> 6;
        int ks = rest % KS, nt = rest / KS;
        int k = ks * 8 + (lane & 3) + reg * 4;
        int n = nt * 8 + (lane >> 2);
        float v = (k < K && n < N) ? W[k * N + n] : 0.f;
        dh[i] = f2tf(v);
    }
}

// ======================= encoder =======================
__global__ __launch_bounds__(ETHREADS, 1)
void encoder_kernel(
    const float* __restrict__ metadata, const float* __restrict__ mask,
    const float* __restrict__ eW1, const float* __restrict__ eb1,
    const float* __restrict__ eg1, const float* __restrict__ ebt1,
    const float* __restrict__ eW2, const float* __restrict__ eb2,
    const float* __restrict__ eg2, const float* __restrict__ ebt2,
    const float* __restrict__ eW3, const float* __restrict__ eb3,
    float* __restrict__ out_latent, int B)
{
    extern __shared__ float sm[];
    uint32_t* smu = (uint32_t*)sm;
    const int tid = threadIdx.x;

    stage_frags<ETHREADS>(smu + EWH,        eW1, 22, 64, 3, 8, tid);
    stage_frags<ETHREADS>(smu + EWH + 1536, eW2, 64, 64, 8, 8, tid);
    stage_frags<ETHREADS>(smu + EWH + 5632, eW3, 64, 32, 8, 4, tid);
    for (int i = tid; i < 64; i += ETHREADS) {
        sm[EPAR + i]       = eb1[i];
        sm[EPAR + 64 + i]  = eg1[i];
        sm[EPAR + 128 + i] = ebt1[i];
        sm[EPAR + 192 + i] = eb2[i];
        sm[EPAR + 256 + i] = eg2[i];
        sm[EPAR + 320 + i] = ebt2[i];
    }
    for (int i = tid; i < 32; i += ETHREADS) sm[EPAR + 384 + i] = eb3[i];
    __syncthreads();

    const int wid = tid >> 5, lane = tid & 31;
    const int g = lane >> 2, tg = lane & 3;
    float* in  = sm + EIN + wid * 448;    // 16 x 28
    float* wkf = sm + EWK + wid * 1088;   // 16 x 68

    for (int rb = ((int)blockIdx.x * EWARPS + wid) * 16; rb < B;
         rb += (int)gridDim.x * EWARPS * 16) {
        for (int i = lane; i < 176; i += 32) {
            int r = i / 11, c = i % 11;
            int gr = min(rb + r, B - 1);
            in[r * 28 + c]      = metadata[(size_t)gr * 11 + c];
            in[r * 28 + 11 + c] = mask[(size_t)gr * 11 + c];
        }
        if (lane < 16) { in[lane * 28 + 22] = 0.f; in[lane * 28 + 23] = 0.f; }
        __syncwarp();

        {   // L1 + LN + GELU
            uint32_t ah[3][4], al[3][4];
            load_af<3>(ah, al, in, 28, g, tg);
            float acc[8][4];
            gemm2_acc<3, 8>(ah, al, smu + EWH, sm + EPAR, acc, lane, tg);
            ln_gelu_store(acc, sm + EPAR + 64, sm + EPAR + 128, wkf, 68, g, tg);
        }
        __syncwarp();
        {   // L2 + LN + GELU
            uint32_t ah[8][4], al[8][4];
            load_af<8>(ah, al, wkf, 68, g, tg);
            float acc[8][4];
            gemm2_acc<8, 8>(ah, al, smu + EWH + 1536, sm + EPAR + 192,
                            acc, lane, tg);
            ln_gelu_store(acc, sm + EPAR + 256, sm + EPAR + 320, wkf, 68, g, tg);
        }
        __syncwarp();
        {   // L3 -> latent
            uint32_t ah[8][4], al[8][4];
            load_af<8>(ah, al, wkf, 68, g, tg);
            gemm2_store<8, 4, false>(ah, al, smu + EWH + 5632, sm + EPAR + 384,
                                     wkf, 68, lane, g, tg);
        }
        __syncwarp();
        for (int i = lane; i < 128; i += 32) {
            int r = i >> 3, q = i & 7;
            int gr = rb + r;
            if (gr < B)
                *(float4*)&out_latent[(size_t)gr * 32 + 4 * q] =
                    *(const float4*)&wkf[r * 68 + 4 * q];
        }
        __syncwarp();
    }
}

// ======================= one flow transform =======================
__global__ __launch_bounds__(FTHREADS, 1)
void flow_kernel(
    const float* __restrict__ latent, const float* __restrict__ prot,
    const float* __restrict__ age,
    const float* __restrict__ fW1t, const float* __restrict__ fb1t,
    const float* __restrict__ fW2t, const float* __restrict__ fb2t,
    const float* __restrict__ fW3t, const float* __restrict__ fb3t,
    int first, int last, float* __restrict__ out_lp, int B)
{
    extern __shared__ float sm[];
    uint32_t* smu = (uint32_t*)sm;
    const int tid = threadIdx.x;

    stage_frags<FTHREADS>(smu + FWH,        fW1t, 33, 64, 5, 8, tid);
    stage_frags<FTHREADS>(smu + FWH + 2560, fW2t, 64, 64, 8, 8, tid);
    stage_frags<FTHREADS>(smu + FWH + 6656, fW3t, 64, 23, 8, 3, tid);
    for (int i = tid; i < 64; i += FTHREADS) {
        sm[FBI + i]      = fb1t[i];
        sm[FBI + 64 + i] = fb2t[i];
    }
    for (int i = tid; i < 32; i += FTHREADS)
        sm[FBI + 128 + i] = (i < 23) ? fb3t[i] : 0.f;
    __syncthreads();

    const int wid = tid >> 5, lane = tid & 31;
    const int g = lane >> 2, tg = lane & 3;
    float* ctx = sm + FCX + wid * 704;   // 16 x 44
    float* wkf = sm + FWK + wid * 1088;  // 16 x 68
    float lsum = 0.f;

    for (int rb = ((int)blockIdx.x * FWARPS + wid) * 16; rb < B;
         rb += (int)gridDim.x * FWARPS * 16) {
        for (int i = lane; i < 128; i += 32) {
            int r = i >> 3, q = i & 7;
            int gr = min(rb + r, B - 1);
            *(float4*)&ctx[r * 44 + 4 * q] =
                *(const float4*)&latent[(size_t)gr * 32 + 4 * q];
        }
        float z = 0.f, la = 0.f;
        if (lane < 16) {
            int gr = min(rb + lane, B - 1);
            ctx[lane * 44 + 32] = prot[gr];
#pragma unroll
            for (int c = 33; c < 40; c++) ctx[lane * 44 + c] = 0.f;
            if (first) { z = age[gr]; la = 0.f; }
            else       { z = g_z[gr]; la = g_ladj[gr]; }
        }
        __syncwarp();

        {   // F1 (ReLU)
            uint32_t ah[5][4], al[5][4];
            load_af<5>(ah, al, ctx, 44, g, tg);
            gemm2_store<5, 8, true>(ah, al, smu + FWH, sm + FBI,
                                    wkf, 68, lane, g, tg);
        }
        __syncwarp();
        {   // F2 (ReLU)
            uint32_t ah[8][4], al[8][4];
            load_af<8>(ah, al, wkf, 68, g, tg);
            gemm2_store<8, 8, true>(ah, al, smu + FWH + 2560, sm + FBI + 64,
                                    wkf, 68, lane, g, tg);
        }
        __syncwarp();
        {   // F3 -> params
            uint32_t ah[8][4], al[8][4];
            load_af<8>(ah, al, wkf, 68, g, tg);
            gemm2_store<8, 3, false>(ah, al, smu + FWH + 6656, sm + FBI + 128,
                                     wkf, 68, lane, g, tg);
        }
        __syncwarp();
        if (lane < 16) {
            int r = rb + lane;
            if (r < B) {
                float p3[24];
#pragma unroll
                for (int c = 0; c < 24; c++) p3[c] = wkf[lane * 68 + c];
                rqs_step(p3, z, la);
                if (last) {
                    float lp = fmaf(-0.5f, z * z, -0.91893853320467274f) + la;
                    out_lp[r] = lp;
                    lsum += lp;
                } else {
                    g_z[r] = z;
                    g_ladj[r] = la;
                }
            }
        }
        __syncwarp();
    }

    if (last) {
        sm[FRED + tid] = lsum;
        __syncthreads();
#pragma unroll
        for (int off = 512; off > 0; off >>= 1) {
            if (tid < off && tid + off < FTHREADS)
                sm[FRED + tid] += sm[FRED + tid + off];
            __syncthreads();
        }
        if (tid == 0) g_block_sums[blockIdx.x] = sm[FRED];
    }
}

__global__ void finalize_kernel(int nblocks, int B, float* __restrict__ out_nll) {
    __shared__ double red[256];
    double s = 0.0;
    for (int i = threadIdx.x; i < nblocks; i += 256)
        s += (double)g_block_sums[i];
    red[threadIdx.x] = s;
    __syncthreads();
#pragma unroll
    for (int off = 128; off > 0; off >>= 1) {
        if (threadIdx.x < off) red[threadIdx.x] += red[threadIdx.x + off];
        __syncthreads();
    }
    if (threadIdx.x == 0)
        out_nll[0] = (float)(-red[0] / (double)B);
}

extern "C" void kernel_launch(void* const* d_in, const int* in_sizes, int n_in,
                              void* d_out, int out_size) {
    const float* metadata = (const float*)d_in[0];
    const float* prot     = (const float*)d_in[1];
    const float* age      = (const float*)d_in[2];
    const float* mask     = (const float*)d_in[3];
    const float* eW1  = (const float*)d_in[4];
    const float* eb1  = (const float*)d_in[5];
    const float* eg1  = (const float*)d_in[6];
    const float* ebt1 = (const float*)d_in[7];
    const float* eW2  = (const float*)d_in[8];
    const float* eb2  = (const float*)d_in[9];
    const float* eg2  = (const float*)d_in[10];
    const float* ebt2 = (const float*)d_in[11];
    const float* eW3  = (const float*)d_in[12];
    const float* eb3  = (const float*)d_in[13];
    const float* fW1  = (const float*)d_in[14];
    const float* fb1  = (const float*)d_in[15];
    const float* fW2  = (const float*)d_in[16];
    const float* fb2  = (const float*)d_in[17];
    const float* fW3  = (const float*)d_in[18];
    const float* fb3  = (const float*)d_in[19];

    const int B = in_sizes[1];
    float* out = (float*)d_out;
    float* out_latent = out;
    float* out_lp     = out + (size_t)B * 32;
    float* out_nll    = out + (size_t)B * 33;

    int sms = 148;
    cudaDeviceProp prop;
    if (cudaGetDeviceProperties(&prop, 0) == cudaSuccess)
        sms = prop.multiProcessorCount;

    size_t enc_smem  = (size_t)ENC_SMW * 4;
    size_t flow_smem = (size_t)FLOW_SMW * 4;
    cudaFuncSetAttribute(encoder_kernel,
                         cudaFuncAttributeMaxDynamicSharedMemorySize,
                         (int)enc_smem);
    cudaFuncSetAttribute(flow_kernel,
                         cudaFuncAttributeMaxDynamicSharedMemorySize,
                         (int)flow_smem);

    // My launch idx: enc(0) f0(1) f1(2) f2(3) f3(4) fin(5).
    // Harness offset is 2 launches -> ncu -s 5 profiles my idx 3 = f2.
    encoder_kernel<<<sms, ETHREADS, enc_smem>>>(
        metadata, mask, eW1, eb1, eg1, ebt1, eW2, eb2, eg2, ebt2, eW3, eb3,
        out_latent, B);

    for (int t = 0; t < 4; t++) {
        flow_kernel<<<sms, FTHREADS, flow_smem>>>(
            out_latent, prot, age,
            fW1 + (size_t)t * 33 * 64, fb1 + (size_t)t * 64,
            fW2 + (size_t)t * 64 * 64, fb2 + (size_t)t * 64,
            fW3 + (size_t)t * 64 * 23, fb3 + (size_t)t * 23,
            (t == 0) ? 1 : 0, (t == 3) ? 1 : 0, out_lp, B);
    }

    finalize_kernel<<<1, 256>>>(sms, B, out_nll);
}